// round 1
// baseline (speedup 1.0000x reference)
#include <cuda_runtime.h>
#include <cuda_bf16.h>
#include <cstdint>

// Problem shape (fixed by the dataset)
#define BATCH 4
#define SEQ   2048
#define NPREV 8
#define DIM   1024
#define HEADS 16
#define HDIM  64                       // DIM / HEADS
#define TOKENS (BATCH * SEQ)           // 8192
#define KVROWS (TOKENS * NPREV)        // 65536

// Scratch (device globals: allocation-free per harness rules)
__device__ float g_q   [(size_t)TOKENS * DIM];   //  33.5 MB
__device__ float g_k   [(size_t)KVROWS * DIM];   // 268.4 MB
__device__ float g_v   [(size_t)KVROWS * DIM];   // 268.4 MB
__device__ float g_attn[(size_t)TOKENS * DIM];   //  33.5 MB

// ---------------------------------------------------------------------------
// SGEMM (NT): C[m,n] = sum_k A[m,k] * B[n,k]  (+ optional addend[m,n])
// A: M x K row-major, B: N x K row-major. M,N,K multiples of tiles.
// 128x128 block, BK=16, 256 threads, 8x8 per-thread register tile.
// ---------------------------------------------------------------------------
#define BM 128
#define BN 128
#define BK 16
#define TM 8
#define TN 8

__global__ __launch_bounds__(256, 2) void sgemm_nt(
    const float* __restrict__ A, const float* __restrict__ B,
    float* __restrict__ C, const float* __restrict__ addend,
    int M, int N, int K)
{
    __shared__ float As[BK][BM + 4];
    __shared__ float Bs[BK][BN + 4];

    const int tid = threadIdx.x;
    const int tx  = tid & 15;          // 0..15  (column group)
    const int ty  = tid >> 4;          // 0..15  (row group)

    const long long blockRow = (long long)blockIdx.y * BM;
    const long long blockCol = (long long)blockIdx.x * BN;

    const float* Ab = A + blockRow * K;
    const float* Bb = B + blockCol * K;

    float acc[TM][TN];
#pragma unroll
    for (int i = 0; i < TM; i++)
#pragma unroll
        for (int j = 0; j < TN; j++) acc[i][j] = 0.f;

    for (int k0 = 0; k0 < K; k0 += BK) {
        // Load 128x16 A-tile and B-tile as float4 (2 per thread each),
        // stored transposed: As[k][m], Bs[k][n].
#pragma unroll
        for (int l = 0; l < 2; l++) {
            const int id = tid + l * 256;       // 0..511
            const int r  = id >> 2;             // 0..127
            const int c4 = id & 3;              // 0..3  (float4 within the 16-wide K slab)
            const float4 va = *reinterpret_cast<const float4*>(Ab + (long long)r * K + k0 + c4 * 4);
            As[c4 * 4 + 0][r] = va.x;
            As[c4 * 4 + 1][r] = va.y;
            As[c4 * 4 + 2][r] = va.z;
            As[c4 * 4 + 3][r] = va.w;
            const float4 vb = *reinterpret_cast<const float4*>(Bb + (long long)r * K + k0 + c4 * 4);
            Bs[c4 * 4 + 0][r] = vb.x;
            Bs[c4 * 4 + 1][r] = vb.y;
            Bs[c4 * 4 + 2][r] = vb.z;
            Bs[c4 * 4 + 3][r] = vb.w;
        }
        __syncthreads();

#pragma unroll
        for (int kk = 0; kk < BK; kk++) {
            float a[TM], b[TN];
#pragma unroll
            for (int i = 0; i < 4; i++) {
                a[i]     = As[kk][ty * 4 + i];
                a[4 + i] = As[kk][64 + ty * 4 + i];
            }
#pragma unroll
            for (int j = 0; j < 4; j++) {
                b[j]     = Bs[kk][tx * 4 + j];
                b[4 + j] = Bs[kk][64 + tx * 4 + j];
            }
#pragma unroll
            for (int i = 0; i < TM; i++)
#pragma unroll
                for (int j = 0; j < TN; j++)
                    acc[i][j] += a[i] * b[j];
        }
        __syncthreads();
    }

    // Epilogue: rows {ty*4+i, 64+ty*4+i}, cols {tx*4+j, 64+tx*4+j}
#pragma unroll
    for (int i = 0; i < TM; i++) {
        const int r = (i < 4) ? (ty * 4 + i) : (64 + ty * 4 + (i - 4));
        const long long grow = blockRow + r;
#pragma unroll
        for (int j = 0; j < TN; j += 4) {
            const int cb = (j < 4) ? (tx * 4) : (64 + tx * 4);
            const long long gcol = blockCol + cb;
            float4 v;
            v.x = acc[i][j + 0];
            v.y = acc[i][j + 1];
            v.z = acc[i][j + 2];
            v.w = acc[i][j + 3];
            if (addend) {
                const float4 ad = *reinterpret_cast<const float4*>(addend + grow * N + gcol);
                v.x += ad.x; v.y += ad.y; v.z += ad.z; v.w += ad.w;
            }
            *reinterpret_cast<float4*>(C + grow * N + gcol) = v;
        }
    }
}

// ---------------------------------------------------------------------------
// Attention: one warp per (token, head). N=8 keys, Hd=64.
// Lane l owns dims {l, l+32}. Logits via warp allreduce; softmax; weighted V.
// ---------------------------------------------------------------------------
__global__ __launch_bounds__(256) void attn_kernel()
{
    const int gw   = (blockIdx.x * blockDim.x + threadIdx.x) >> 5;  // global warp id
    const int lane = threadIdx.x & 31;
    const int h = gw & (HEADS - 1);
    const int t = gw >> 4;                                          // token index

    const size_t qoff = (size_t)t * DIM + h * HDIM;
    const float q0 = g_q[qoff + lane];
    const float q1 = g_q[qoff + lane + 32];

    float logits[NPREV];
#pragma unroll
    for (int n = 0; n < NPREV; n++) {
        const size_t koff = ((size_t)t * NPREV + n) * DIM + h * HDIM;
        float p = q0 * g_k[koff + lane] + q1 * g_k[koff + lane + 32];
#pragma unroll
        for (int off = 16; off > 0; off >>= 1)
            p += __shfl_xor_sync(0xFFFFFFFFu, p, off);
        logits[n] = p * 0.125f;   // 1/sqrt(64)
    }

    float mx = logits[0];
#pragma unroll
    for (int n = 1; n < NPREV; n++) mx = fmaxf(mx, logits[n]);
    float w[NPREV];
    float den = 0.f;
#pragma unroll
    for (int n = 0; n < NPREV; n++) {
        w[n] = __expf(logits[n] - mx);
        den += w[n];
    }
    const float inv = 1.f / den;

    float o0 = 0.f, o1 = 0.f;
#pragma unroll
    for (int n = 0; n < NPREV; n++) {
        const size_t voff = ((size_t)t * NPREV + n) * DIM + h * HDIM;
        o0 += w[n] * g_v[voff + lane];
        o1 += w[n] * g_v[voff + lane + 32];
    }
    g_attn[qoff + lane]      = o0 * inv;
    g_attn[qoff + lane + 32] = o1 * inv;
}

// ---------------------------------------------------------------------------
// Launch
// ---------------------------------------------------------------------------
extern "C" void kernel_launch(void* const* d_in, const int* in_sizes, int n_in,
                              void* d_out, int out_size)
{
    const float* current = (const float*)d_in[0];   // (B,S,D)
    const float* history = (const float*)d_in[1];   // (B,S,N,D)
    const float* Wq      = (const float*)d_in[2];   // (D,D)
    const float* Wk      = (const float*)d_in[3];
    const float* Wv      = (const float*)d_in[4];
    const float* Wo      = (const float*)d_in[5];
    float*       out     = (float*)d_out;

    float *q_p, *k_p, *v_p, *attn_p;
    cudaGetSymbolAddress((void**)&q_p,    g_q);
    cudaGetSymbolAddress((void**)&k_p,    g_k);
    cudaGetSymbolAddress((void**)&v_p,    g_v);
    cudaGetSymbolAddress((void**)&attn_p, g_attn);

    const dim3 blk(256);

    // 1) q = current @ Wq^T      (8192 x 1024 x 1024)
    sgemm_nt<<<dim3(DIM / BN, TOKENS / BM), blk>>>(current, Wq, q_p, nullptr,
                                                   TOKENS, DIM, DIM);
    // 2) k = history @ Wk^T      (65536 x 1024 x 1024)
    sgemm_nt<<<dim3(DIM / BN, KVROWS / BM), blk>>>(history, Wk, k_p, nullptr,
                                                   KVROWS, DIM, DIM);
    // 3) v = history @ Wv^T
    sgemm_nt<<<dim3(DIM / BN, KVROWS / BM), blk>>>(history, Wv, v_p, nullptr,
                                                   KVROWS, DIM, DIM);
    // 4) attention -> g_attn     (131072 warps)
    attn_kernel<<<(TOKENS * HEADS) / 8, blk>>>();
    // 5) out = current + attn @ Wo^T
    sgemm_nt<<<dim3(DIM / BN, TOKENS / BM), blk>>>(attn_p, Wo, out, current,
                                                   TOKENS, DIM, DIM);
}

// round 3
// speedup vs baseline: 2.7395x; 2.7395x over previous
#include <cuda_runtime.h>
#include <cuda_bf16.h>
#include <cstdint>
#include <cstddef>

// ---------------------------------------------------------------- problem shape
#define BATCH 4
#define SEQ   2048
#define NPREV 8
#define DIM   1024
#define HEADS 16
#define HDIM  64
#define TOKENS (BATCH * SEQ)           // 8192
#define KVROWS (TOKENS * NPREV)        // 65536

// ---------------------------------------------------------------- scratch
__device__ float g_q[(size_t)TOKENS * DIM];
__device__ float g_k[(size_t)KVROWS * DIM];
__device__ float g_v[(size_t)KVROWS * DIM];

__device__ __nv_bfloat16 g_cur_hi [(size_t)TOKENS * DIM];
__device__ __nv_bfloat16 g_cur_lo [(size_t)TOKENS * DIM];
__device__ __nv_bfloat16 g_hist_hi[(size_t)KVROWS * DIM];
__device__ __nv_bfloat16 g_hist_lo[(size_t)KVROWS * DIM];
__device__ __nv_bfloat16 g_attn_hi[(size_t)TOKENS * DIM];
__device__ __nv_bfloat16 g_attn_lo[(size_t)TOKENS * DIM];
__device__ __nv_bfloat16 g_w_hi[4u * DIM * DIM];
__device__ __nv_bfloat16 g_w_lo[4u * DIM * DIM];

// ---------------------------------------------------------------- helpers
__device__ __forceinline__ uint32_t smem_u32(const void* p) {
    uint32_t a;
    asm("{ .reg .u64 t; cvta.to.shared.u64 t, %1; cvt.u32.u64 %0, t; }" : "=r"(a) : "l"(p));
    return a;
}
__device__ __forceinline__ uint32_t swz(uint32_t off) { return off ^ ((off >> 3) & 0x70); }

__device__ __forceinline__ void cpasync16(uint32_t s, const void* g) {
    asm volatile("cp.async.cg.shared.global [%0], [%1], 16;" :: "r"(s), "l"(g));
}
__device__ __forceinline__ void cp_commit() {
    asm volatile("cp.async.commit_group;" ::: "memory");
}
template <int N>
__device__ __forceinline__ void cp_wait() {
    asm volatile("cp.async.wait_group %0;" :: "n"(N) : "memory");
}

__device__ __forceinline__ void ldsm_x4(uint32_t& r0, uint32_t& r1, uint32_t& r2, uint32_t& r3,
                                        uint32_t addr) {
    asm volatile("ldmatrix.sync.aligned.m8n8.x4.shared.b16 {%0,%1,%2,%3}, [%4];"
                 : "=r"(r0), "=r"(r1), "=r"(r2), "=r"(r3) : "r"(addr));
}

__device__ __forceinline__ void mma16816(float* d, const uint32_t* a, const uint32_t* b) {
    asm volatile(
        "mma.sync.aligned.m16n8k16.row.col.f32.bf16.bf16.f32 "
        "{%0,%1,%2,%3}, {%4,%5,%6,%7}, {%8,%9}, {%0,%1,%2,%3};"
        : "+f"(d[0]), "+f"(d[1]), "+f"(d[2]), "+f"(d[3])
        : "r"(a[0]), "r"(a[1]), "r"(a[2]), "r"(a[3]), "r"(b[0]), "r"(b[1]));
}

// ---------------------------------------------------------------- GEMM (HMMA bf16x3)
// C[M,1024] = Ahi*Bhi^T + Ahi*Blo^T + Alo*Bhi^T (+addend). A,B K-major bf16.
// CTA tile 128x128, BK=64, 3-stage cp.async pipeline, 8 warps (warp tile 32x64).
#define GBM 128
#define GBN 128
#define CK  64
#define NCHUNK (DIM / CK)                 // 16
#define MAT_BYTES (128 * 128)             // one 128-row x 128B sub-matrix = 16 KB
#define STAGE_BYTES (4 * MAT_BYTES)       // Ahi, Alo, Bhi, Blo = 64 KB
#define NSTAGE 3
#define SMEM_DYN (NSTAGE * STAGE_BYTES)   // 192 KB

__device__ __forceinline__ void load_stage(
    uint32_t sbase, int tid,
    const char* Ahi, const char* Alo, const char* Bhi, const char* Blo,
    long long m0, long long n0, int chunk)
{
    const long long kbyte = (long long)chunk * 128;     // 64 bf16 = 128 B
#pragma unroll
    for (int i = 0; i < 4; i++) {
        const int u  = tid + i * 256;     // 0..1023
        const int r  = u >> 3;            // row 0..127
        const int c8 = u & 7;             // 16B chunk in row
        const uint32_t so = swz((uint32_t)(r * 128 + c8 * 16));
        const long long ga = (m0 + r) * (DIM * 2) + kbyte + c8 * 16;
        const long long gb = (n0 + r) * (DIM * 2) + kbyte + c8 * 16;
        cpasync16(sbase + 0 * MAT_BYTES + so, Ahi + ga);
        cpasync16(sbase + 1 * MAT_BYTES + so, Alo + ga);
        cpasync16(sbase + 2 * MAT_BYTES + so, Bhi + gb);
        cpasync16(sbase + 3 * MAT_BYTES + so, Blo + gb);
    }
}

__global__ __launch_bounds__(256, 1) void gemm_hmma(
    const __nv_bfloat16* __restrict__ Ahi, const __nv_bfloat16* __restrict__ Alo,
    const __nv_bfloat16* __restrict__ Bhi, const __nv_bfloat16* __restrict__ Blo,
    float* __restrict__ C, const float* __restrict__ addend)
{
    extern __shared__ char dynsmem[];
    const uint32_t base = smem_u32(dynsmem);

    const int tid    = threadIdx.x;
    const int lane   = tid & 31;
    const int wid    = tid >> 5;
    const int warp_m = wid & 3;           // 0..3 -> m offset 32*warp_m
    const int warp_n = wid >> 2;          // 0..1 -> n offset 64*warp_n

    const long long m0 = (long long)blockIdx.y * GBM;
    const long long n0 = (long long)blockIdx.x * GBN;

    const char* pAhi = (const char*)Ahi;
    const char* pAlo = (const char*)Alo;
    const char* pBhi = (const char*)Bhi;
    const char* pBlo = (const char*)Blo;

    float acc[2][8][4];
#pragma unroll
    for (int mt = 0; mt < 2; mt++)
#pragma unroll
        for (int nt = 0; nt < 8; nt++)
#pragma unroll
            for (int j = 0; j < 4; j++) acc[mt][nt][j] = 0.f;

    // Prologue: stages 0,1
    load_stage(base + 0 * STAGE_BYTES, tid, pAhi, pAlo, pBhi, pBlo, m0, n0, 0);
    cp_commit();
    load_stage(base + 1 * STAGE_BYTES, tid, pAhi, pAlo, pBhi, pBlo, m0, n0, 1);
    cp_commit();

    // Per-lane ldmatrix address offsets (within a sub-matrix, before stage/mat bases)
    // A: rows warp_m*32 + mt*16 + (lane&15), colbyte s*32 + (lane&16 ? 16 : 0)
    const int a_row  = warp_m * 32 + (lane & 15);
    const int a_cofs = (lane & 16) ? 16 : 0;
    // B: rows warp_n*64 + nb + (lane&7) + (lane&16 ? 8 : 0), colbyte s*32 + (lane&8 ? 16 : 0)
    const int b_row  = warp_n * 64 + (lane & 7) + ((lane & 16) ? 8 : 0);
    const int b_cofs = (lane & 8) ? 16 : 0;

    for (int c = 0; c < NCHUNK; ++c) {
        if (c + 2 < NCHUNK) cp_wait<1>(); else cp_wait<0>();
        __syncthreads();
        if (c + 2 < NCHUNK) {
            load_stage(base + ((c + 2) % NSTAGE) * STAGE_BYTES, tid,
                       pAhi, pAlo, pBhi, pBlo, m0, n0, c + 2);
            cp_commit();
        }

        const uint32_t sA_hi = base + (c % NSTAGE) * STAGE_BYTES;
        const uint32_t sA_lo = sA_hi + MAT_BYTES;
        const uint32_t sB_hi = sA_hi + 2 * MAT_BYTES;
        const uint32_t sB_lo = sA_hi + 3 * MAT_BYTES;

#pragma unroll
        for (int s = 0; s < 4; s++) {                    // k16 steps within BK=64
            uint32_t ah[2][4], al[2][4], bh[8][2], bl[8][2];
#pragma unroll
            for (int mt = 0; mt < 2; mt++) {
                const uint32_t off = swz((uint32_t)((a_row + mt * 16) * 128 + s * 32 + a_cofs));
                ldsm_x4(ah[mt][0], ah[mt][1], ah[mt][2], ah[mt][3], sA_hi + off);
                ldsm_x4(al[mt][0], al[mt][1], al[mt][2], al[mt][3], sA_lo + off);
            }
#pragma unroll
            for (int np = 0; np < 4; np++) {             // pairs of n8 tiles
                const uint32_t off = swz((uint32_t)((b_row + np * 16) * 128 + s * 32 + b_cofs));
                uint32_t r0, r1, r2, r3;
                ldsm_x4(r0, r1, r2, r3, sB_hi + off);
                bh[np * 2][0] = r0; bh[np * 2][1] = r1;
                bh[np * 2 + 1][0] = r2; bh[np * 2 + 1][1] = r3;
                ldsm_x4(r0, r1, r2, r3, sB_lo + off);
                bl[np * 2][0] = r0; bl[np * 2][1] = r1;
                bl[np * 2 + 1][0] = r2; bl[np * 2 + 1][1] = r3;
            }
#pragma unroll
            for (int mt = 0; mt < 2; mt++)
#pragma unroll
                for (int nt = 0; nt < 8; nt++) {
                    mma16816(acc[mt][nt], ah[mt], bh[nt]);
                    mma16816(acc[mt][nt], ah[mt], bl[nt]);
                    mma16816(acc[mt][nt], al[mt], bh[nt]);
                }
        }
        __syncthreads();
    }

    // Epilogue: c0,c1 -> row g, cols 2t,2t+1 ; c2,c3 -> row g+8
    const int g = lane >> 2;
    const int t = lane & 3;
#pragma unroll
    for (int mt = 0; mt < 2; mt++) {
#pragma unroll
        for (int half = 0; half < 2; half++) {
            const long long row = m0 + warp_m * 32 + mt * 16 + g + half * 8;
            float* crow = C + row * DIM + n0 + warp_n * 64;
            const float* arow = addend ? (addend + row * DIM + n0 + warp_n * 64) : nullptr;
#pragma unroll
            for (int nt = 0; nt < 8; nt++) {
                float2 v;
                v.x = acc[mt][nt][half * 2 + 0];
                v.y = acc[mt][nt][half * 2 + 1];
                if (arow) {
                    const float2 a = *reinterpret_cast<const float2*>(arow + nt * 8 + 2 * t);
                    v.x += a.x; v.y += a.y;
                }
                *reinterpret_cast<float2*>(crow + nt * 8 + 2 * t) = v;
            }
        }
    }
}

// ---------------------------------------------------------------- split fp32 -> bf16 hi/lo
__global__ __launch_bounds__(256) void split_bf16_kernel(
    const float4* __restrict__ x, __nv_bfloat162* __restrict__ hi,
    __nv_bfloat162* __restrict__ lo, int n4)
{
    const int i = blockIdx.x * blockDim.x + threadIdx.x;
    if (i >= n4) return;
    const float4 v = x[i];
    const __nv_bfloat16 h0 = __float2bfloat16(v.x);
    const __nv_bfloat16 h1 = __float2bfloat16(v.y);
    const __nv_bfloat16 h2 = __float2bfloat16(v.z);
    const __nv_bfloat16 h3 = __float2bfloat16(v.w);
    const __nv_bfloat16 l0 = __float2bfloat16(v.x - __bfloat162float(h0));
    const __nv_bfloat16 l1 = __float2bfloat16(v.y - __bfloat162float(h1));
    const __nv_bfloat16 l2 = __float2bfloat16(v.z - __bfloat162float(h2));
    const __nv_bfloat16 l3 = __float2bfloat16(v.w - __bfloat162float(h3));
    hi[i * 2 + 0] = __nv_bfloat162(h0, h1);
    hi[i * 2 + 1] = __nv_bfloat162(h2, h3);
    lo[i * 2 + 0] = __nv_bfloat162(l0, l1);
    lo[i * 2 + 1] = __nv_bfloat162(l2, l3);
}

// ---------------------------------------------------------------- attention
__global__ __launch_bounds__(256) void attn_kernel()
{
    const int gw   = (blockIdx.x * blockDim.x + threadIdx.x) >> 5;
    const int lane = threadIdx.x & 31;
    const int h = gw & (HEADS - 1);
    const int t = gw >> 4;

    const size_t qoff = (size_t)t * DIM + h * HDIM;
    const float q0 = g_q[qoff + lane];
    const float q1 = g_q[qoff + lane + 32];

    float logits[NPREV];
#pragma unroll
    for (int n = 0; n < NPREV; n++) {
        const size_t koff = ((size_t)t * NPREV + n) * DIM + h * HDIM;
        float p = q0 * g_k[koff + lane] + q1 * g_k[koff + lane + 32];
#pragma unroll
        for (int off = 16; off > 0; off >>= 1)
            p += __shfl_xor_sync(0xFFFFFFFFu, p, off);
        logits[n] = p * 0.125f;
    }

    float mx = logits[0];
#pragma unroll
    for (int n = 1; n < NPREV; n++) mx = fmaxf(mx, logits[n]);
    float w[NPREV];
    float den = 0.f;
#pragma unroll
    for (int n = 0; n < NPREV; n++) { w[n] = __expf(logits[n] - mx); den += w[n]; }
    const float inv = 1.f / den;

    float o0 = 0.f, o1 = 0.f;
#pragma unroll
    for (int n = 0; n < NPREV; n++) {
        const size_t voff = ((size_t)t * NPREV + n) * DIM + h * HDIM;
        o0 += w[n] * g_v[voff + lane];
        o1 += w[n] * g_v[voff + lane + 32];
    }
    o0 *= inv; o1 *= inv;

    const __nv_bfloat16 h0 = __float2bfloat16(o0);
    const __nv_bfloat16 h1 = __float2bfloat16(o1);
    g_attn_hi[qoff + lane]      = h0;
    g_attn_hi[qoff + lane + 32] = h1;
    g_attn_lo[qoff + lane]      = __float2bfloat16(o0 - __bfloat162float(h0));
    g_attn_lo[qoff + lane + 32] = __float2bfloat16(o1 - __bfloat162float(h1));
}

// ---------------------------------------------------------------- launch
extern "C" void kernel_launch(void* const* d_in, const int* in_sizes, int n_in,
                              void* d_out, int out_size)
{
    const float* current = (const float*)d_in[0];
    const float* history = (const float*)d_in[1];
    const float* Wq      = (const float*)d_in[2];
    const float* Wk      = (const float*)d_in[3];
    const float* Wv      = (const float*)d_in[4];
    const float* Wo      = (const float*)d_in[5];
    float*       out     = (float*)d_out;

    float *q_p, *k_p, *v_p;
    __nv_bfloat16 *cur_hi, *cur_lo, *hist_hi, *hist_lo, *attn_hi, *attn_lo, *w_hi, *w_lo;
    cudaGetSymbolAddress((void**)&q_p,     g_q);
    cudaGetSymbolAddress((void**)&k_p,     g_k);
    cudaGetSymbolAddress((void**)&v_p,     g_v);
    cudaGetSymbolAddress((void**)&cur_hi,  g_cur_hi);
    cudaGetSymbolAddress((void**)&cur_lo,  g_cur_lo);
    cudaGetSymbolAddress((void**)&hist_hi, g_hist_hi);
    cudaGetSymbolAddress((void**)&hist_lo, g_hist_lo);
    cudaGetSymbolAddress((void**)&attn_hi, g_attn_hi);
    cudaGetSymbolAddress((void**)&attn_lo, g_attn_lo);
    cudaGetSymbolAddress((void**)&w_hi,    g_w_hi);
    cudaGetSymbolAddress((void**)&w_lo,    g_w_lo);

    cudaFuncSetAttribute(gemm_hmma, cudaFuncAttributeMaxDynamicSharedMemorySize, SMEM_DYN);

    const size_t WN = (size_t)DIM * DIM;

    // splits
    {
        const int n4c = TOKENS * DIM / 4;
        split_bf16_kernel<<<(n4c + 255) / 256, 256>>>(
            (const float4*)current, (__nv_bfloat162*)cur_hi, (__nv_bfloat162*)cur_lo, n4c);
        const int n4h = (int)((size_t)KVROWS * DIM / 4);
        split_bf16_kernel<<<(n4h + 255) / 256, 256>>>(
            (const float4*)history, (__nv_bfloat162*)hist_hi, (__nv_bfloat162*)hist_lo, n4h);
        const int n4w = (int)(WN / 4);
        const float* Ws[4] = {Wq, Wk, Wv, Wo};
        for (int i = 0; i < 4; i++)
            split_bf16_kernel<<<(n4w + 255) / 256, 256>>>(
                (const float4*)Ws[i],
                (__nv_bfloat162*)(w_hi + i * WN), (__nv_bfloat162*)(w_lo + i * WN), n4w);
    }

    // projections
    gemm_hmma<<<dim3(DIM / GBN, TOKENS / GBM), 256, SMEM_DYN>>>(
        cur_hi, cur_lo, w_hi + 0 * WN, w_lo + 0 * WN, q_p, nullptr);
    gemm_hmma<<<dim3(DIM / GBN, KVROWS / GBM), 256, SMEM_DYN>>>(
        hist_hi, hist_lo, w_hi + 1 * WN, w_lo + 1 * WN, k_p, nullptr);
    gemm_hmma<<<dim3(DIM / GBN, KVROWS / GBM), 256, SMEM_DYN>>>(
        hist_hi, hist_lo, w_hi + 2 * WN, w_lo + 2 * WN, v_p, nullptr);

    // attention
    attn_kernel<<<(TOKENS * HEADS) / 8, 256>>>();

    // output projection + residual
    gemm_hmma<<<dim3(DIM / GBN, TOKENS / GBM), 256, SMEM_DYN>>>(
        attn_hi, attn_lo, w_hi + 3 * WN, w_lo + 3 * WN, out, current);
}

// round 5
// speedup vs baseline: 7.0310x; 2.5665x over previous
#include <cuda_runtime.h>
#include <cuda_fp16.h>
#include <cstdint>
#include <cstddef>

// ---------------------------------------------------------------- problem shape
#define BATCH 4
#define SEQ   2048
#define NPREV 8
#define DIM   1024
#define HEADS 16
#define HDIM  64
#define TOKENS (BATCH * SEQ)           // 8192
#define KVROWS (TOKENS * NPREV)        // 65536

// ---------------------------------------------------------------- scratch (fp16)
__device__ __half g_cur16 [(size_t)TOKENS * DIM];
__device__ __half g_hist16[(size_t)KVROWS * DIM];
__device__ __half g_w16[4u * DIM * DIM];
__device__ __half g_q16 [(size_t)TOKENS * DIM];
__device__ __half g_k16 [(size_t)KVROWS * DIM];
__device__ __half g_v16 [(size_t)KVROWS * DIM];
__device__ __half g_attn16[(size_t)TOKENS * DIM];

// ---------------------------------------------------------------- helpers
__device__ __forceinline__ uint32_t smem_u32(const void* p) {
    uint32_t a;
    asm("{ .reg .u64 t; cvta.to.shared.u64 t, %1; cvt.u32.u64 %0, t; }" : "=r"(a) : "l"(p));
    return a;
}
__device__ __forceinline__ uint32_t swz(uint32_t off) { return off ^ ((off >> 3) & 0x70); }

__device__ __forceinline__ void cpasync16(uint32_t s, const void* g) {
    asm volatile("cp.async.cg.shared.global [%0], [%1], 16;" :: "r"(s), "l"(g));
}
__device__ __forceinline__ void cp_commit() {
    asm volatile("cp.async.commit_group;" ::: "memory");
}
template <int N>
__device__ __forceinline__ void cp_wait() {
    asm volatile("cp.async.wait_group %0;" :: "n"(N) : "memory");
}

__device__ __forceinline__ void ldsm_x4(uint32_t& r0, uint32_t& r1, uint32_t& r2, uint32_t& r3,
                                        uint32_t addr) {
    asm volatile("ldmatrix.sync.aligned.m8n8.x4.shared.b16 {%0,%1,%2,%3}, [%4];"
                 : "=r"(r0), "=r"(r1), "=r"(r2), "=r"(r3) : "r"(addr));
}

__device__ __forceinline__ void mma16816_f16(float* d, const uint32_t* a, const uint32_t* b) {
    asm volatile(
        "mma.sync.aligned.m16n8k16.row.col.f32.f16.f16.f32 "
        "{%0,%1,%2,%3}, {%4,%5,%6,%7}, {%8,%9}, {%0,%1,%2,%3};"
        : "+f"(d[0]), "+f"(d[1]), "+f"(d[2]), "+f"(d[3])
        : "r"(a[0]), "r"(a[1]), "r"(a[2]), "r"(a[3]), "r"(b[0]), "r"(b[1]));
}

// ---------------------------------------------------------------- GEMM (fp16 single pass)
// C[M,N=1024] = A * B^T (+addend).  A: MxK fp16 row-major, B: NxK fp16 row-major.
// CTA tile 128x128, BK=64, 3-stage cp.async pipeline, 8 warps (warp tile 32x64).
#define GBM 128
#define GBN 128
#define NCHUNK (DIM / 64)                 // 16
#define MAT_BYTES (128 * 128)             // 128 rows x 128B = 16 KB
#define STAGE_BYTES (2 * MAT_BYTES)       // A + B = 32 KB
#define NSTAGE 3
#define SMEM_DYN (NSTAGE * STAGE_BYTES)   // 96 KB -> 2 CTAs/SM

__device__ __forceinline__ void load_stage(
    uint32_t sbase, int tid, const char* A, const char* B,
    long long m0, long long n0, int chunk)
{
    const long long kbyte = (long long)chunk * 128;     // 64 fp16 = 128 B
#pragma unroll
    for (int i = 0; i < 4; i++) {
        const int u  = tid + i * 256;     // 0..1023
        const int r  = u >> 3;            // row 0..127
        const int c8 = u & 7;             // 16B chunk within 128B row
        const uint32_t so = swz((uint32_t)(r * 128 + c8 * 16));
        cpasync16(sbase + so,             A + (m0 + r) * (DIM * 2) + kbyte + c8 * 16);
        cpasync16(sbase + MAT_BYTES + so, B + (n0 + r) * (DIM * 2) + kbyte + c8 * 16);
    }
}

template <bool F16OUT>
__global__ __launch_bounds__(256, 2) void gemm_f16(
    const __half* __restrict__ A, const __half* __restrict__ B,
    void* __restrict__ Cout, const float* __restrict__ addend)
{
    extern __shared__ char dynsmem[];
    const uint32_t base = smem_u32(dynsmem);

    const int tid    = threadIdx.x;
    const int lane   = tid & 31;
    const int wid    = tid >> 5;
    const int warp_m = wid & 3;
    const int warp_n = wid >> 2;

    const long long m0 = (long long)blockIdx.y * GBM;
    const long long n0 = (long long)blockIdx.x * GBN;
    const char* pA = (const char*)A;
    const char* pB = (const char*)B;

    float acc[2][8][4];
#pragma unroll
    for (int mt = 0; mt < 2; mt++)
#pragma unroll
        for (int nt = 0; nt < 8; nt++)
#pragma unroll
            for (int j = 0; j < 4; j++) acc[mt][nt][j] = 0.f;

    load_stage(base + 0 * STAGE_BYTES, tid, pA, pB, m0, n0, 0);
    cp_commit();
    load_stage(base + 1 * STAGE_BYTES, tid, pA, pB, m0, n0, 1);
    cp_commit();

    const int a_row  = warp_m * 32 + (lane & 15);
    const int a_cofs = (lane & 16) ? 16 : 0;
    const int b_row  = warp_n * 64 + (lane & 7) + ((lane & 16) ? 8 : 0);
    const int b_cofs = (lane & 8) ? 16 : 0;

    for (int c = 0; c < NCHUNK; ++c) {
        if (c + 2 < NCHUNK) cp_wait<1>(); else cp_wait<0>();
        __syncthreads();
        if (c + 2 < NCHUNK) {
            load_stage(base + ((c + 2) % NSTAGE) * STAGE_BYTES, tid, pA, pB, m0, n0, c + 2);
            cp_commit();
        }

        const uint32_t sA = base + (c % NSTAGE) * STAGE_BYTES;
        const uint32_t sB = sA + MAT_BYTES;

#pragma unroll
        for (int s = 0; s < 4; s++) {
            uint32_t af[2][4], bf[8][2];
#pragma unroll
            for (int mt = 0; mt < 2; mt++) {
                const uint32_t off = swz((uint32_t)((a_row + mt * 16) * 128 + s * 32 + a_cofs));
                ldsm_x4(af[mt][0], af[mt][1], af[mt][2], af[mt][3], sA + off);
            }
#pragma unroll
            for (int np = 0; np < 4; np++) {
                const uint32_t off = swz((uint32_t)((b_row + np * 16) * 128 + s * 32 + b_cofs));
                uint32_t r0, r1, r2, r3;
                ldsm_x4(r0, r1, r2, r3, sB + off);
                bf[np * 2][0] = r0;     bf[np * 2][1] = r1;
                bf[np * 2 + 1][0] = r2; bf[np * 2 + 1][1] = r3;
            }
#pragma unroll
            for (int mt = 0; mt < 2; mt++)
#pragma unroll
                for (int nt = 0; nt < 8; nt++)
                    mma16816_f16(acc[mt][nt], af[mt], bf[nt]);
        }
        __syncthreads();
    }

    // Epilogue. acc pairs: {c0,c1}->row g, {c2,c3}->row g+8, cols nt*8 + 2t.
    const int g = lane >> 2;
    const int t = lane & 3;
#pragma unroll
    for (int mt = 0; mt < 2; mt++) {
#pragma unroll
        for (int half = 0; half < 2; half++) {
            const long long row = m0 + warp_m * 32 + mt * 16 + g + half * 8;
            const long long colbase = n0 + warp_n * 64;
            if (F16OUT) {
                __half* crow = (__half*)Cout + row * DIM + colbase;
#pragma unroll
                for (int nt = 0; nt < 8; nt++) {
                    const __half2 v = __floats2half2_rn(acc[mt][nt][half * 2 + 0],
                                                        acc[mt][nt][half * 2 + 1]);
                    *reinterpret_cast<__half2*>(crow + nt * 8 + 2 * t) = v;
                }
            } else {
                float* crow = (float*)Cout + row * DIM + colbase;
                const float* arow = addend + row * DIM + colbase;
#pragma unroll
                for (int nt = 0; nt < 8; nt++) {
                    float2 v;
                    v.x = acc[mt][nt][half * 2 + 0];
                    v.y = acc[mt][nt][half * 2 + 1];
                    const float2 a = *reinterpret_cast<const float2*>(arow + nt * 8 + 2 * t);
                    v.x += a.x; v.y += a.y;
                    *reinterpret_cast<float2*>(crow + nt * 8 + 2 * t) = v;
                }
            }
        }
    }
}

// ---------------------------------------------------------------- fp32 -> fp16 convert
__global__ __launch_bounds__(256) void tohalf_kernel(
    const float4* __restrict__ x, __half2* __restrict__ y, int n4)
{
    const int i = blockIdx.x * blockDim.x + threadIdx.x;
    if (i >= n4) return;
    const float4 v = x[i];
    y[i * 2 + 0] = __floats2half2_rn(v.x, v.y);
    y[i * 2 + 1] = __floats2half2_rn(v.z, v.w);
}

// ---------------------------------------------------------------- attention (fp16 I/O)
// One warp per (token, head). Lane l owns dims {2l, 2l+1} via __half2.
__global__ __launch_bounds__(256) void attn_kernel()
{
    const int gw   = (blockIdx.x * blockDim.x + threadIdx.x) >> 5;
    const int lane = threadIdx.x & 31;
    const int h = gw & (HEADS - 1);
    const int t = gw >> 4;

    const size_t qoff = (size_t)t * DIM + h * HDIM;
    const float2 qv = __half22float2(reinterpret_cast<const __half2*>(g_q16 + qoff)[lane]);

    float logits[NPREV];
#pragma unroll
    for (int n = 0; n < NPREV; n++) {
        const size_t koff = ((size_t)t * NPREV + n) * DIM + h * HDIM;
        const float2 kv = __half22float2(reinterpret_cast<const __half2*>(g_k16 + koff)[lane]);
        float p = qv.x * kv.x + qv.y * kv.y;
#pragma unroll
        for (int off = 16; off > 0; off >>= 1)
            p += __shfl_xor_sync(0xFFFFFFFFu, p, off);
        logits[n] = p * 0.125f;
    }

    float mx = logits[0];
#pragma unroll
    for (int n = 1; n < NPREV; n++) mx = fmaxf(mx, logits[n]);
    float w[NPREV];
    float den = 0.f;
#pragma unroll
    for (int n = 0; n < NPREV; n++) { w[n] = __expf(logits[n] - mx); den += w[n]; }
    const float inv = 1.f / den;

    float o0 = 0.f, o1 = 0.f;
#pragma unroll
    for (int n = 0; n < NPREV; n++) {
        const size_t voff = ((size_t)t * NPREV + n) * DIM + h * HDIM;
        const float2 vv = __half22float2(reinterpret_cast<const __half2*>(g_v16 + voff)[lane]);
        o0 += w[n] * vv.x;
        o1 += w[n] * vv.y;
    }
    reinterpret_cast<__half2*>(g_attn16 + qoff)[lane] = __floats2half2_rn(o0 * inv, o1 * inv);
}

// ---------------------------------------------------------------- launch
extern "C" void kernel_launch(void* const* d_in, const int* in_sizes, int n_in,
                              void* d_out, int out_size)
{
    const float* current = (const float*)d_in[0];
    const float* history = (const float*)d_in[1];
    const float* Wq      = (const float*)d_in[2];
    const float* Wk      = (const float*)d_in[3];
    const float* Wv      = (const float*)d_in[4];
    const float* Wo      = (const float*)d_in[5];
    float*       out     = (float*)d_out;

    __half *cur16, *hist16, *w16, *q16, *k16, *v16, *attn16;
    cudaGetSymbolAddress((void**)&cur16,  g_cur16);
    cudaGetSymbolAddress((void**)&hist16, g_hist16);
    cudaGetSymbolAddress((void**)&w16,    g_w16);
    cudaGetSymbolAddress((void**)&q16,    g_q16);
    cudaGetSymbolAddress((void**)&k16,    g_k16);
    cudaGetSymbolAddress((void**)&v16,    g_v16);
    cudaGetSymbolAddress((void**)&attn16, g_attn16);

    cudaFuncSetAttribute(gemm_f16<true>,  cudaFuncAttributeMaxDynamicSharedMemorySize, SMEM_DYN);
    cudaFuncSetAttribute(gemm_f16<false>, cudaFuncAttributeMaxDynamicSharedMemorySize, SMEM_DYN);

    const size_t WN = (size_t)DIM * DIM;

    // fp32 -> fp16 converts
    {
        const int n4c = TOKENS * DIM / 4;
        tohalf_kernel<<<(n4c + 255) / 256, 256>>>((const float4*)current, (__half2*)cur16, n4c);
        const int n4h = (int)((size_t)KVROWS * DIM / 4);
        tohalf_kernel<<<(n4h + 255) / 256, 256>>>((const float4*)history, (__half2*)hist16, n4h);
        const int n4w = (int)(WN / 4);
        const float* Ws[4] = {Wq, Wk, Wv, Wo};
        for (int i = 0; i < 4; i++)
            tohalf_kernel<<<(n4w + 255) / 256, 256>>>(
                (const float4*)Ws[i], (__half2*)(w16 + i * WN), n4w);
    }

    // projections: q,k,v written as fp16
    gemm_f16<true><<<dim3(DIM / GBN, TOKENS / GBM), 256, SMEM_DYN>>>(
        cur16, w16 + 0 * WN, q16, nullptr);
    gemm_f16<true><<<dim3(DIM / GBN, KVROWS / GBM), 256, SMEM_DYN>>>(
        hist16, w16 + 1 * WN, k16, nullptr);
    gemm_f16<true><<<dim3(DIM / GBN, KVROWS / GBM), 256, SMEM_DYN>>>(
        hist16, w16 + 2 * WN, v16, nullptr);

    // attention
    attn_kernel<<<(TOKENS * HEADS) / 8, 256>>>();

    // output projection + residual (fp32 out)
    gemm_f16<false><<<dim3(DIM / GBN, TOKENS / GBM), 256, SMEM_DYN>>>(
        attn16, w16 + 3 * WN, out, current);
}